// round 2
// baseline (speedup 1.0000x reference)
#include <cuda_runtime.h>
#include <cuda_bf16.h>
#include <cstdint>

// ===================== problem constants =====================
// x: (128, 64, 8, 2048) fp32 == 262144 rows of 128 (row = (b,i,r,p,g))
// W: (8, 128, 128), b: (8, 128)
// Per 256 consecutive rows the channel i is constant; CTA takes 128 rows.
#define N_DIM      128
#define K_DIM      128
#define ROWS_CTA   128
#define K_CHUNK    64
#define THREADS    256
#define NUM_CTAS   2048          // 262144 / 128
#define S          68            // smem row stride in words (68 mod 32 == 4 -> conflict-free frags)

// SMEM: [W chunk 128 x S][A chunk 128 x S][bias 128]
#define SM_W_OFF   0
#define SM_A_OFF   (128 * S)
#define SM_B_OFF   (2 * 128 * S)
#define SMEM_FLOATS (2 * 128 * S + 128)
#define SMEM_BYTES  (SMEM_FLOATS * 4)   // 70144

// ===================== helpers =====================
__device__ __forceinline__ uint32_t rna_tf32_bits(float f) {
    uint32_t r;
    asm("cvt.rna.tf32.f32 %0, %1;" : "=r"(r) : "f"(f));
    return r;
}
__device__ __forceinline__ float rna_tf32(float f) {
    uint32_t r = rna_tf32_bits(f);
    return __uint_as_float(r);
}

// m16n8k8 tf32 MMA, D/C fp32 (4 regs), A 4 regs, B 2 regs
__device__ __forceinline__ void mma_tf32(float* c, const uint32_t* a, const uint32_t* b) {
    asm volatile(
        "mma.sync.aligned.m16n8k8.row.col.f32.tf32.tf32.f32 "
        "{%0,%1,%2,%3}, {%4,%5,%6,%7}, {%8,%9}, {%0,%1,%2,%3};"
        : "+f"(c[0]), "+f"(c[1]), "+f"(c[2]), "+f"(c[3])
        : "r"(a[0]), "r"(a[1]), "r"(a[2]), "r"(a[3]),
          "r"(b[0]), "r"(b[1]));
}

// ===================== W pre-rounded image =====================
__device__ __align__(16) float g_Wrnd[8 * 128 * 128];

__global__ void prep_w_kernel(const float* __restrict__ W) {
    int idx = blockIdx.x * blockDim.x + threadIdx.x;   // 0 .. 131071
    if (idx < 8 * 128 * 128)
        g_Wrnd[idx] = rna_tf32(W[idx]);
}

// ===================== main GEMM =====================
__global__ __launch_bounds__(THREADS, 2)
void gemm_kernel(const float* __restrict__ x, const float* __restrict__ bias,
                 float* __restrict__ out) {
    extern __shared__ __align__(16) float smem[];
    float* sW = smem + SM_W_OFF;
    float* sA = smem + SM_A_OFF;
    float* sB = smem + SM_B_OFF;

    const int tid  = threadIdx.x;
    const int lane = tid & 31;
    const int wid  = tid >> 5;
    const int blk  = blockIdx.x;
    const int ch   = (blk >> 1) & 7;          // 256 rows per (b,i) block -> 2 CTAs per block

    const float* a_base = x + (size_t)blk * (ROWS_CTA * K_DIM);
    float*       o_base = out + (size_t)blk * (ROWS_CTA * N_DIM);
    const float* w_base = g_Wrnd + ch * (N_DIM * K_DIM);

    if (tid < 128) sB[tid] = bias[ch * 128 + tid];

    // warp tiling: 4 warps over M (32 rows each), 2 over N (64 cols each)
    const int warpM = (wid >> 1) * 32;
    const int warpN = (wid & 1) * 64;

    float acc[2][8][4];
#pragma unroll
    for (int mt = 0; mt < 2; mt++)
#pragma unroll
        for (int nt = 0; nt < 8; nt++)
#pragma unroll
            for (int q = 0; q < 4; q++) acc[mt][nt][q] = 0.0f;

    // fragment base pointers (lane-fixed)
    const float* aF = sA + (warpM + (lane >> 2)) * S + (lane & 3);
    const float* bF = sW + (warpN + (lane >> 2)) * S + (lane & 3);

#pragma unroll
    for (int kc = 0; kc < 2; kc++) {
        // ---- load W chunk (pre-rounded, L2-resident) ----
#pragma unroll
        for (int j = 0; j < 8; j++) {
            int f = j * THREADS + tid;         // 0..2047 float4s
            int n = f >> 4, q = (f & 15) << 2;
            float4 v = *(const float4*)(w_base + n * K_DIM + kc * K_CHUNK + q);
            *(float4*)(sW + n * S + q) = v;
        }
        // ---- load A chunk (fp32 -> RNA tf32) ----
#pragma unroll
        for (int j = 0; j < 8; j++) {
            int f = j * THREADS + tid;
            int r = f >> 4, q = (f & 15) << 2;
            float4 v = *(const float4*)(a_base + r * K_DIM + kc * K_CHUNK + q);
            v.x = rna_tf32(v.x);
            v.y = rna_tf32(v.y);
            v.z = rna_tf32(v.z);
            v.w = rna_tf32(v.w);
            *(float4*)(sA + r * S + q) = v;
        }
        __syncthreads();

        // ---- MMA over this K chunk: 8 k-steps of k=8 ----
#pragma unroll
        for (int ks = 0; ks < 8; ks++) {
            uint32_t afr[2][4];
#pragma unroll
            for (int mt = 0; mt < 2; mt++) {
                const float* ap = aF + mt * 16 * S + ks * 8;
                afr[mt][0] = __float_as_uint(ap[0]);
                afr[mt][1] = __float_as_uint(ap[8 * S]);
                afr[mt][2] = __float_as_uint(ap[4]);
                afr[mt][3] = __float_as_uint(ap[8 * S + 4]);
            }
#pragma unroll
            for (int nt = 0; nt < 8; nt++) {
                const float* bp = bF + nt * 8 * S + ks * 8;
                uint32_t bfr[2];
                bfr[0] = __float_as_uint(bp[0]);
                bfr[1] = __float_as_uint(bp[4]);
                mma_tf32(acc[0][nt], afr[0], bfr);
                mma_tf32(acc[1][nt], afr[1], bfr);
            }
        }
        __syncthreads();   // before next chunk overwrites smem
    }

    // ---- epilogue: accum + bias -> gmem (float2, full 32B sectors) ----
    const int r0 = warpM + (lane >> 2);
    const int n0 = warpN + (lane & 3) * 2;
#pragma unroll
    for (int mt = 0; mt < 2; mt++) {
#pragma unroll
        for (int h = 0; h < 2; h++) {          // h=0 -> row, h=1 -> row+8
            int row = r0 + mt * 16 + h * 8;
            float* orow = o_base + (size_t)row * N_DIM;
#pragma unroll
            for (int nt = 0; nt < 8; nt++) {
                int n = n0 + nt * 8;
                float2 v;
                v.x = acc[mt][nt][h * 2 + 0] + sB[n];
                v.y = acc[mt][nt][h * 2 + 1] + sB[n + 1];
                *(float2*)(orow + n) = v;
            }
        }
    }
}

// ===================== launch =====================
extern "C" void kernel_launch(void* const* d_in, const int* in_sizes, int n_in,
                              void* d_out, int out_size) {
    const float* x = (const float*)d_in[0];
    const float* W = (const float*)d_in[1];
    const float* b = (const float*)d_in[2];
    float* out = (float*)d_out;

    cudaFuncSetAttribute(gemm_kernel, cudaFuncAttributeMaxDynamicSharedMemorySize, SMEM_BYTES);

    prep_w_kernel<<<512, 256>>>(W);
    gemm_kernel<<<NUM_CTAS, THREADS, SMEM_BYTES>>>(x, b, out);
}

// round 3
// speedup vs baseline: 1.2786x; 1.2786x over previous
#include <cuda_runtime.h>
#include <cuda_bf16.h>
#include <cstdint>

// ===================== problem constants =====================
// x: 262144 rows x 128 (row = (b,i,r,p,g)); W: (8,128,128); b: (8,128)
// CTA: 128 rows (M) x 128 cols (N) x K=128. Channel constant per 256 rows.
#define N_DIM      128
#define K_DIM      128
#define ROWS_CTA   128
#define THREADS    256
#define NUM_CTAS   2048
#define K_CHUNK    32
#define NCHUNK     4
#define STAGES     3

// ---- smem layout (floats) ----
#define SA_STRIDE  36                       // 36 mod 32 == 4 -> conflict-free frag reads
#define SA_FLOATS  (128 * SA_STRIDE)        // 4608
#define SW_FLOATS  4096                     // W chunk fragment image: 128 x 32
#define STAGE_FLOATS (SA_FLOATS + SW_FLOATS)  // 8704
#define SM_BIAS_OFF  (STAGES * STAGE_FLOATS)  // 26112
#define SMEM_FLOATS  (SM_BIAS_OFF + 128)
#define SMEM_BYTES   (SMEM_FLOATS * 4)        // 104,960

// ===================== helpers =====================
__device__ __forceinline__ uint32_t smem_u32(const void* p) {
    uint32_t a;
    asm("{ .reg .u64 t; cvta.to.shared.u64 t, %1; cvt.u32.u64 %0, t; }" : "=r"(a) : "l"(p));
    return a;
}
__device__ __forceinline__ uint32_t rna_tf32_u(float f) {
    uint32_t r;
    asm("cvt.rna.tf32.f32 %0, %1;" : "=r"(r) : "f"(f));
    return r;
}
__device__ __forceinline__ float rna_tf32(float f) { return __uint_as_float(rna_tf32_u(f)); }

__device__ __forceinline__ void cp_async16(uint32_t dst, const void* src) {
    asm volatile("cp.async.cg.shared.global [%0], [%1], 16;" :: "r"(dst), "l"(src));
}
#define CP_COMMIT()  asm volatile("cp.async.commit_group;" ::: "memory")
#define CP_WAIT(n)   asm volatile("cp.async.wait_group %0;" :: "n"(n) : "memory")

__device__ __forceinline__ void mma_tf32(float* c, const uint32_t* a, uint32_t b0, uint32_t b1) {
    asm volatile(
        "mma.sync.aligned.m16n8k8.row.col.f32.tf32.tf32.f32 "
        "{%0,%1,%2,%3}, {%4,%5,%6,%7}, {%8,%9}, {%0,%1,%2,%3};"
        : "+f"(c[0]), "+f"(c[1]), "+f"(c[2]), "+f"(c[3])
        : "r"(a[0]), "r"(a[1]), "r"(a[2]), "r"(a[3]), "r"(b0), "r"(b1));
}

// ===================== W fragment image =====================
// Per (ch, kc): 4096-float image. For warp half h (warpN=64h), ntpair p, kstep ks:
// float4 at f4-index [h*512 + p*128 + ks*32 + lane] =
//   { W[c0][k], W[c0][k+4], W[c0+8][k], W[c0+8][k+4] }
// with c0 = 64h + 16p + (lane>>2), k = kc*32 + ks*8 + (lane&3).
__device__ __align__(16) float g_Wimg[8 * K_DIM * N_DIM];

__global__ void prep_w_kernel(const float* __restrict__ W) {
    int idx = blockIdx.x * blockDim.x + threadIdx.x;   // 0 .. 131071
    if (idx >= 8 * 128 * 128) return;
    int ch = idx >> 14;
    int n  = (idx >> 7) & 127;   // output feature (B column)
    int k  = idx & 127;
    int h = n >> 6, colh = n & 63;
    int p = colh >> 4, ntodd = (colh >> 3) & 1, cs = colh & 7;
    int kc = k >> 5, kk = k & 31;
    int ks = kk >> 3, klo = kk & 3, khi = (kk >> 2) & 1;
    int fi = (((h * 4 + p) * 4 + ks) * 8 + cs) * 16 + klo * 4 + ntodd * 2 + khi;
    g_Wimg[(ch * 4 + kc) * SW_FLOATS + fi] = rna_tf32(W[idx]);
}

// ===================== stage loader =====================
__device__ __forceinline__ void load_stage(uint32_t sm_base, int stage,
                                           const float* a_base, const float* wimg_ch,
                                           int kc, int tid) {
    uint32_t sa = sm_base + (uint32_t)(stage * STAGE_FLOATS) * 4u;
    uint32_t sw = sa + SA_FLOATS * 4u;
    // A chunk: 128 rows x 32 floats = 1024 x 16B pieces
#pragma unroll
    for (int j = 0; j < 4; j++) {
        int pid = j * THREADS + tid;
        int r = pid >> 3, pc = pid & 7;
        cp_async16(sa + (uint32_t)(r * SA_STRIDE + pc * 4) * 4u,
                   a_base + r * K_DIM + kc * K_CHUNK + pc * 4);
    }
    // W chunk image: verbatim 16KB
    const float* wsrc = wimg_ch + kc * SW_FLOATS;
#pragma unroll
    for (int j = 0; j < 4; j++) {
        int pid = j * THREADS + tid;
        cp_async16(sw + (uint32_t)pid * 16u, wsrc + pid * 4);
    }
    CP_COMMIT();
}

// ===================== main GEMM =====================
__global__ __launch_bounds__(THREADS, 2)
void gemm_kernel(const float* __restrict__ x, const float* __restrict__ bias,
                 float* __restrict__ out) {
    extern __shared__ __align__(16) float smem[];
    const uint32_t sm_base = smem_u32(smem);

    const int tid  = threadIdx.x;
    const int lane = tid & 31;
    const int wid  = tid >> 5;
    const int blk  = blockIdx.x;
    const int ch   = (blk >> 1) & 7;

    const float* a_base  = x + (size_t)blk * (ROWS_CTA * K_DIM);
    float*       o_base  = out + (size_t)blk * (ROWS_CTA * N_DIM);
    const float* wimg_ch = g_Wimg + ch * (K_DIM * N_DIM);

    if (tid < 128) smem[SM_BIAS_OFF + tid] = bias[ch * 128 + tid];

    // warp tiling: 4 warps over M (32 rows), 2 over N (64 cols)
    const int warpM = (wid >> 1) * 32;
    const int h     = (wid & 1);          // N half

    float acc[2][8][4];
#pragma unroll
    for (int mt = 0; mt < 2; mt++)
#pragma unroll
        for (int nt = 0; nt < 8; nt++)
#pragma unroll
            for (int q = 0; q < 4; q++) acc[mt][nt][q] = 0.0f;

    // prologue: prefetch stages 0,1
    load_stage(sm_base, 0, a_base, wimg_ch, 0, tid);
    load_stage(sm_base, 1, a_base, wimg_ch, 1, tid);

    const int aoff = (warpM + (lane >> 2)) * SA_STRIDE + (lane & 3);

#pragma unroll
    for (int kc = 0; kc < NCHUNK; kc++) {
        if (kc < NCHUNK - 1) { CP_WAIT(1); } else { CP_WAIT(0); }
        __syncthreads();
        if (kc + 2 < NCHUNK)
            load_stage(sm_base, (kc + 2) % STAGES, a_base, wimg_ch, kc + 2, tid);

        const float* sa = smem + (kc % STAGES) * STAGE_FLOATS;
        const float4* bW = (const float4*)(sa + SA_FLOATS) + h * 512 + lane;
        const float* aF = sa + aoff;

#pragma unroll
        for (int ks = 0; ks < 4; ks++) {
            uint32_t afr[2][4];
#pragma unroll
            for (int mt = 0; mt < 2; mt++) {
                const float* ap = aF + mt * 16 * SA_STRIDE + ks * 8;
                afr[mt][0] = rna_tf32_u(ap[0]);
                afr[mt][1] = rna_tf32_u(ap[8 * SA_STRIDE]);
                afr[mt][2] = rna_tf32_u(ap[4]);
                afr[mt][3] = rna_tf32_u(ap[8 * SA_STRIDE + 4]);
            }
#pragma unroll
            for (int p = 0; p < 4; p++) {
                float4 f = bW[p * 128 + ks * 32];
                uint32_t b0x = __float_as_uint(f.x), b0y = __float_as_uint(f.y);
                uint32_t b1x = __float_as_uint(f.z), b1y = __float_as_uint(f.w);
                mma_tf32(acc[0][2 * p],     afr[0], b0x, b0y);
                mma_tf32(acc[0][2 * p + 1], afr[0], b1x, b1y);
                mma_tf32(acc[1][2 * p],     afr[1], b0x, b0y);
                mma_tf32(acc[1][2 * p + 1], afr[1], b1x, b1y);
            }
        }
    }

    // ---- epilogue: accum + bias -> gmem (float2, full 32B sectors) ----
    const float* sB = smem + SM_BIAS_OFF;
    const int r0 = warpM + (lane >> 2);
    const int n0 = h * 64 + (lane & 3) * 2;
#pragma unroll
    for (int mt = 0; mt < 2; mt++) {
#pragma unroll
        for (int hh = 0; hh < 2; hh++) {
            int row = r0 + mt * 16 + hh * 8;
            float* orow = o_base + (size_t)row * N_DIM;
#pragma unroll
            for (int nt = 0; nt < 8; nt++) {
                int n = n0 + nt * 8;
                float2 v;
                v.x = acc[mt][nt][hh * 2 + 0] + sB[n];
                v.y = acc[mt][nt][hh * 2 + 1] + sB[n + 1];
                *(float2*)(orow + n) = v;
            }
        }
    }
}

// ===================== launch =====================
extern "C" void kernel_launch(void* const* d_in, const int* in_sizes, int n_in,
                              void* d_out, int out_size) {
    const float* x = (const float*)d_in[0];
    const float* W = (const float*)d_in[1];
    const float* b = (const float*)d_in[2];
    float* out = (float*)d_out;

    cudaFuncSetAttribute(gemm_kernel, cudaFuncAttributeMaxDynamicSharedMemorySize, SMEM_BYTES);

    prep_w_kernel<<<512, 256>>>(W);
    gemm_kernel<<<NUM_CTAS, THREADS, SMEM_BYTES>>>(x, b, out);
}